// round 15
// baseline (speedup 1.0000x reference)
#include <cuda_runtime.h>
#include <cuda_fp16.h>
#include <cstdint>

#define BQ   2
#define SEQ  2048
#define DIMC 1024
#define NH   16
#define DH   64
#define QKVC 3072
#define NROWS (BQ*SEQ)
#define PITCH 2056

// ---- device scratch ----
__device__ float  g_xn[(size_t)NROWS * DIMC];            // 16 MB
__device__ float  g_qkv[(size_t)NROWS * QKVC];           // 48 MB  [q | k | v]
__device__ float  g_dots[(size_t)BQ * NH * SEQ * SEQ];   // 512 MB (raw dots)
__device__ __half g_prh[(size_t)BQ * NH * SEQ * SEQ];    // 256 MB (post-mix probs fp16)
__device__ float  g_ao[(size_t)BQ * NH * SEQ * DH];      // 16 MB  [b,g,i,d]

__device__ __forceinline__ uint32_t f2tf32(float f) {
    uint32_t u; asm("cvt.rna.tf32.f32 %0, %1;" : "=r"(u) : "f"(f)); return u;
}
__device__ __forceinline__ void spl(float v, uint32_t& h, uint32_t& l) {
    uint32_t hb = f2tf32(v);
    h = hb;
    l = f2tf32(v - __uint_as_float(hb));
}

#define MMA_TF32(c, a, b) \
    asm volatile("mma.sync.aligned.m16n8k8.row.col.f32.tf32.tf32.f32 " \
        "{%0,%1,%2,%3}, {%4,%5,%6,%7}, {%8,%9}, {%0,%1,%2,%3};" \
        : "+f"((c)[0]), "+f"((c)[1]), "+f"((c)[2]), "+f"((c)[3]) \
        : "r"((a)[0]), "r"((a)[1]), "r"((a)[2]), "r"((a)[3]), \
          "r"((b)[0]), "r"((b)[1]))

// ============================================================ LayerNorm
__global__ void ln_kernel(const float* __restrict__ x,
                          const float* __restrict__ gamma,
                          const float* __restrict__ beta) {
    int row = blockIdx.x;
    int t = threadIdx.x;
    const float4* xr = (const float4*)(x + (size_t)row * DIMC);
    float4 v = xr[t];
    float s = v.x + v.y + v.z + v.w;
    float q = v.x*v.x + v.y*v.y + v.z*v.z + v.w*v.w;
    __shared__ float s_sum[8], s_sq[8];
    #pragma unroll
    for (int o = 16; o > 0; o >>= 1) {
        s += __shfl_xor_sync(0xffffffffu, s, o);
        q += __shfl_xor_sync(0xffffffffu, q, o);
    }
    if ((t & 31) == 0) { s_sum[t >> 5] = s; s_sq[t >> 5] = q; }
    __syncthreads();
    if (t < 32) {
        float a = (t < 8) ? s_sum[t] : 0.f;
        float c = (t < 8) ? s_sq[t] : 0.f;
        #pragma unroll
        for (int o = 4; o > 0; o >>= 1) {
            a += __shfl_xor_sync(0xffffffffu, a, o);
            c += __shfl_xor_sync(0xffffffffu, c, o);
        }
        if (t == 0) { s_sum[0] = a; s_sq[0] = c; }
    }
    __syncthreads();
    float mean = s_sum[0] * (1.f / DIMC);
    float var  = s_sq[0] * (1.f / DIMC) - mean * mean;
    float rs = rsqrtf(var + 1e-5f);
    float4 gg = ((const float4*)gamma)[t];
    float4 bb = ((const float4*)beta)[t];
    float4 o;
    o.x = (v.x - mean) * rs * gg.x + bb.x;
    o.y = (v.y - mean) * rs * gg.y + bb.y;
    o.z = (v.z - mean) * rs * gg.z + bb.z;
    o.w = (v.w - mean) * rs * gg.w + bb.w;
    ((float4*)(g_xn + (size_t)row * DIMC))[t] = o;
}

// ============================================================ QKV projection (TF32 MMA, R2 engine)
__global__ __launch_bounds__(256)
void proj_mma_kernel(const float* __restrict__ Wq, const float* __restrict__ Wkv) {
    __shared__ uint32_t As[16][136];
    __shared__ uint32_t Bs[16][136];
    int t = threadIdx.x, lane = t & 31, w = t >> 5;
    int wm = (w & 1) * 64, wn = (w >> 1) * 32;
    int cb = blockIdx.x * 128;
    const float* Bp; int ldb;
    if (cb < 1024) { Bp = Wq; ldb = 1024; } else { Bp = Wkv; ldb = 2048; cb -= 1024; }
    int m0 = blockIdx.y * 128;
    int sa_m = t >> 1, sa_k = (t & 1) * 8;
    int sb_k = t >> 4, sb_n = (t & 15) * 8;
    const float* Aptr = g_xn + (size_t)(m0 + sa_m) * DIMC + sa_k;
    const float* Bptr = Bp + (size_t)sb_k * ldb + cb + sb_n;
    float c[4][4][4] = {};
    for (int kk = 0; kk < DIMC; kk += 16) {
        float4 a0 = *(const float4*)Aptr;
        float4 a1 = *(const float4*)(Aptr + 4);
        Aptr += 16;
        float4 b0 = *(const float4*)Bptr;
        float4 b1 = *(const float4*)(Bptr + 4);
        Bptr += (size_t)16 * ldb;
        As[sa_k+0][sa_m] = f2tf32(a0.x); As[sa_k+1][sa_m] = f2tf32(a0.y);
        As[sa_k+2][sa_m] = f2tf32(a0.z); As[sa_k+3][sa_m] = f2tf32(a0.w);
        As[sa_k+4][sa_m] = f2tf32(a1.x); As[sa_k+5][sa_m] = f2tf32(a1.y);
        As[sa_k+6][sa_m] = f2tf32(a1.z); As[sa_k+7][sa_m] = f2tf32(a1.w);
        *(uint4*)&Bs[sb_k][sb_n]   = make_uint4(f2tf32(b0.x), f2tf32(b0.y), f2tf32(b0.z), f2tf32(b0.w));
        *(uint4*)&Bs[sb_k][sb_n+4] = make_uint4(f2tf32(b1.x), f2tf32(b1.y), f2tf32(b1.z), f2tf32(b1.w));
        __syncthreads();
        #pragma unroll
        for (int ks = 0; ks < 2; ks++) {
            int kr = ks * 8 + (lane & 3);
            int mr = wm + (lane >> 2);
            int nr = wn + (lane >> 2);
            uint32_t af[4][4], bf[4][2];
            #pragma unroll
            for (int mt = 0; mt < 4; mt++) {
                af[mt][0] = As[kr][mr + mt*16];
                af[mt][1] = As[kr][mr + mt*16 + 8];
                af[mt][2] = As[kr+4][mr + mt*16];
                af[mt][3] = As[kr+4][mr + mt*16 + 8];
            }
            #pragma unroll
            for (int nt = 0; nt < 4; nt++) {
                bf[nt][0] = Bs[kr][nr + nt*8];
                bf[nt][1] = Bs[kr+4][nr + nt*8];
            }
            #pragma unroll
            for (int mt = 0; mt < 4; mt++)
                #pragma unroll
                for (int nt = 0; nt < 4; nt++)
                    MMA_TF32(c[mt][nt], af[mt], bf[nt]);
        }
        __syncthreads();
    }
    int col0 = blockIdx.x * 128 + wn + 2 * (lane & 3);
    int row0 = m0 + wm + (lane >> 2);
    #pragma unroll
    for (int mt = 0; mt < 4; mt++)
        #pragma unroll
        for (int nt = 0; nt < 4; nt++) {
            float* Cp = g_qkv + (size_t)(row0 + mt*16) * QKVC + col0 + nt*8;
            *(float2*)Cp = make_float2(c[mt][nt][0], c[mt][nt][1]);
            *(float2*)(Cp + (size_t)8 * QKVC) = make_float2(c[mt][nt][2], c[mt][nt][3]);
        }
}

// ============================================================ S = scale * Q K^T (per batch)
__global__ __launch_bounds__(256)
void qk_mma_kernel(int b) {
    __shared__ uint32_t As[16][136];
    __shared__ uint32_t Bs[16][136];
    int t = threadIdx.x, lane = t & 31, w = t >> 5;
    int wm = (w & 1) * 64, wn = (w >> 1) * 32;
    int h = blockIdx.z, z = b * 16 + h;
    const float* Qb = g_qkv + (size_t)b * SEQ * QKVC + h * DH;
    const float* Kb = Qb + 1024;
    int m0 = blockIdx.y * 128, n0 = blockIdx.x * 128;
    int sm = t >> 1, sk = (t & 1) * 8;
    const float* Ap  = Qb + (size_t)(m0 + sm) * QKVC + sk;
    const float* Bp  = Kb + (size_t)(n0 + sm) * QKVC + sk;
    float c[4][4][4] = {};
    for (int kk = 0; kk < DH; kk += 16) {
        float4 a0 = *(const float4*)Ap;
        float4 a1 = *(const float4*)(Ap + 4);
        Ap += 16;
        float4 k0 = *(const float4*)Bp;
        float4 k1 = *(const float4*)(Bp + 4);
        Bp += 16;
        As[sk+0][sm] = f2tf32(a0.x); As[sk+1][sm] = f2tf32(a0.y);
        As[sk+2][sm] = f2tf32(a0.z); As[sk+3][sm] = f2tf32(a0.w);
        As[sk+4][sm] = f2tf32(a1.x); As[sk+5][sm] = f2tf32(a1.y);
        As[sk+6][sm] = f2tf32(a1.z); As[sk+7][sm] = f2tf32(a1.w);
        Bs[sk+0][sm] = f2tf32(k0.x); Bs[sk+1][sm] = f2tf32(k0.y);
        Bs[sk+2][sm] = f2tf32(k0.z); Bs[sk+3][sm] = f2tf32(k0.w);
        Bs[sk+4][sm] = f2tf32(k1.x); Bs[sk+5][sm] = f2tf32(k1.y);
        Bs[sk+6][sm] = f2tf32(k1.z); Bs[sk+7][sm] = f2tf32(k1.w);
        __syncthreads();
        #pragma unroll
        for (int ks = 0; ks < 2; ks++) {
            int kr = ks * 8 + (lane & 3);
            int mr = wm + (lane >> 2);
            int nr = wn + (lane >> 2);
            uint32_t af[4][4], bf[4][2];
            #pragma unroll
            for (int mt = 0; mt < 4; mt++) {
                af[mt][0] = As[kr][mr + mt*16];
                af[mt][1] = As[kr][mr + mt*16 + 8];
                af[mt][2] = As[kr+4][mr + mt*16];
                af[mt][3] = As[kr+4][mr + mt*16 + 8];
            }
            #pragma unroll
            for (int nt = 0; nt < 4; nt++) {
                bf[nt][0] = Bs[kr][nr + nt*8];
                bf[nt][1] = Bs[kr+4][nr + nt*8];
            }
            #pragma unroll
            for (int mt = 0; mt < 4; mt++)
                #pragma unroll
                for (int nt = 0; nt < 4; nt++)
                    MMA_TF32(c[mt][nt], af[mt], bf[nt]);
        }
        __syncthreads();
    }
    const float scale = 0.125f;
    int col0 = n0 + wn + 2 * (lane & 3);
    int row0 = m0 + wm + (lane >> 2);
    #pragma unroll
    for (int mt = 0; mt < 4; mt++)
        #pragma unroll
        for (int nt = 0; nt < 4; nt++) {
            float* Cp = g_dots + ((size_t)z * SEQ + row0 + mt*16) * SEQ + col0 + nt*8;
            *(float2*)Cp = make_float2(c[mt][nt][0]*scale, c[mt][nt][1]*scale);
            *(float2*)(Cp + (size_t)8 * SEQ) = make_float2(c[mt][nt][2]*scale, c[mt][nt][3]*scale);
        }
}

// ============================================================ mix (MMA) -> softmax -> mix (MMA) (per batch)
// 512 threads (16 warps); reads g_dots f32, writes g_prh fp16
__global__ __launch_bounds__(512)
void mixsoftmax_kernel(const float* __restrict__ mix_pre, const float* __restrict__ mix_post,
                       int b) {
    extern __shared__ float srow[];          // [NH][PITCH]
    __shared__ float mps[256], mqs[256];
    __shared__ float red[NH][16];
    __shared__ float mg[NH], ssum[NH], linv[NH];
    int t = threadIdx.x, lane = t & 31, w = t >> 5;
    int g0 = lane >> 2, h0 = lane & 3;
    int i = blockIdx.x;
    if (t < 256) { mps[t] = mix_pre[t]; mqs[t] = mix_post[t]; }
    size_t base = ((size_t)(b * NH) * SEQ + i) * SEQ;
    for (int h = 0; h < NH; h++) {
        const float4* src = (const float4*)(g_dots + base + (size_t)h * SEQ * SEQ);
        float4* dst = (float4*)(srow + h * PITCH);
        for (int j = t; j < SEQ/4; j += 512) dst[j] = src[j];
    }
    __syncthreads();

    uint32_t pah[2][4], pal[2][4];
    #pragma unroll
    for (int ks = 0; ks < 2; ks++) {
        int hh = h0 + ks * 8;
        spl(mps[hh*16 + g0],        pah[ks][0], pal[ks][0]);
        spl(mps[hh*16 + g0 + 8],    pah[ks][1], pal[ks][1]);
        spl(mps[(hh+4)*16 + g0],    pah[ks][2], pal[ks][2]);
        spl(mps[(hh+4)*16 + g0 + 8],pah[ks][3], pal[ks][3]);
    }
    float pm0 = -3.4e38f, pm1 = -3.4e38f;
    for (int tile = 0; tile < 16; tile++) {
        int j0 = (w * 16 + tile) * 8;
        int col = j0 + g0;
        uint32_t bh[2][2], bl[2][2];
        spl(srow[h0*PITCH + col],        bh[0][0], bl[0][0]);
        spl(srow[(h0+4)*PITCH + col],    bh[0][1], bl[0][1]);
        spl(srow[(h0+8)*PITCH + col],    bh[1][0], bl[1][0]);
        spl(srow[(h0+12)*PITCH + col],   bh[1][1], bl[1][1]);
        float c[4] = {0.f, 0.f, 0.f, 0.f};
        #pragma unroll
        for (int ks = 0; ks < 2; ks++) {
            MMA_TF32(c, pah[ks], bh[ks]);
            MMA_TF32(c, pah[ks], bl[ks]);
            MMA_TF32(c, pal[ks], bh[ks]);
        }
        __syncwarp();
        *(float2*)&srow[g0*PITCH + j0 + 2*h0]     = make_float2(c[0], c[1]);
        *(float2*)&srow[(g0+8)*PITCH + j0 + 2*h0] = make_float2(c[2], c[3]);
        pm0 = fmaxf(pm0, fmaxf(c[0], c[1]));
        pm1 = fmaxf(pm1, fmaxf(c[2], c[3]));
    }
    pm0 = fmaxf(pm0, __shfl_xor_sync(0xffffffffu, pm0, 1));
    pm0 = fmaxf(pm0, __shfl_xor_sync(0xffffffffu, pm0, 2));
    pm1 = fmaxf(pm1, __shfl_xor_sync(0xffffffffu, pm1, 1));
    pm1 = fmaxf(pm1, __shfl_xor_sync(0xffffffffu, pm1, 2));
    if (h0 == 0) { red[g0][w] = pm0; red[g0 + 8][w] = pm1; }
    __syncthreads();
    if (t < NH) {
        float v = red[t][0];
        #pragma unroll
        for (int w2 = 1; w2 < 16; w2++) v = fmaxf(v, red[t][w2]);
        mg[t] = v;
    }
    __syncthreads();
    {
        int r = w;
        float m = mg[r];
        float s = 0.f;
        float* rp = srow + r * PITCH;
        #pragma unroll 4
        for (int i2 = 0; i2 < 16; i2++) {
            int j4 = (lane + i2 * 32) * 4;
            float4 v = *(float4*)&rp[j4];
            v.x = __expf(v.x - m); v.y = __expf(v.y - m);
            v.z = __expf(v.z - m); v.w = __expf(v.w - m);
            s += (v.x + v.y) + (v.z + v.w);
            *(float4*)&rp[j4] = v;
        }
        #pragma unroll
        for (int o = 16; o > 0; o >>= 1) s += __shfl_xor_sync(0xffffffffu, s, o);
        if (lane == 0) ssum[r] = s;
    }
    __syncthreads();
    if (t < NH) linv[t] = 1.f / ssum[t];
    __syncthreads();
    uint32_t qah[2][4], qal[2][4];
    #pragma unroll
    for (int ks = 0; ks < 2; ks++) {
        int hh = h0 + ks * 8;
        spl(mqs[hh*16 + g0]         * linv[hh],   qah[ks][0], qal[ks][0]);
        spl(mqs[hh*16 + g0 + 8]     * linv[hh],   qah[ks][1], qal[ks][1]);
        spl(mqs[(hh+4)*16 + g0]     * linv[hh+4], qah[ks][2], qal[ks][2]);
        spl(mqs[(hh+4)*16 + g0 + 8] * linv[hh+4], qah[ks][3], qal[ks][3]);
    }
    for (int tile = 0; tile < 16; tile++) {
        int j0 = (w * 16 + tile) * 8;
        int col = j0 + g0;
        uint32_t bh[2][2], bl[2][2];
        spl(srow[h0*PITCH + col],        bh[0][0], bl[0][0]);
        spl(srow[(h0+4)*PITCH + col],    bh[0][1], bl[0][1]);
        spl(srow[(h0+8)*PITCH + col],    bh[1][0], bl[1][0]);
        spl(srow[(h0+12)*PITCH + col],   bh[1][1], bl[1][1]);
        float c[4] = {0.f, 0.f, 0.f, 0.f};
        #pragma unroll
        for (int ks = 0; ks < 2; ks++) {
            MMA_TF32(c, qah[ks], bh[ks]);
            MMA_TF32(c, qah[ks], bl[ks]);
            MMA_TF32(c, qal[ks], bh[ks]);
        }
        __half* Cp = g_prh + base + (size_t)g0 * SEQ * SEQ + j0 + 2*h0;
        *(__half2*)Cp = __floats2half2_rn(c[0], c[1]);
        *(__half2*)(Cp + (size_t)8 * SEQ * SEQ) = __floats2half2_rn(c[2], c[3]);
    }
}

// ============================================================ O = P @ V  (per batch; CTA 128x64, 4 warps 64x32; A fp16)
__global__ __launch_bounds__(128)
void av_mma_kernel(int b) {
    __shared__ uint32_t As[16][136];
    __shared__ uint32_t Bs[16][72];
    int t = threadIdx.x, lane = t & 31, w = t >> 5;
    int wm = (w & 1) * 64, wn = (w >> 1) * 32;
    int g = blockIdx.y, z = b * 16 + g;
    const __half* Am = g_prh + (size_t)z * SEQ * SEQ;
    const float* Vb = g_qkv + (size_t)b * SEQ * QKVC + 2048 + g * DH;
    int m0 = blockIdx.x * 128;
    const __half* Arow = Am + (size_t)(m0 + t) * SEQ;
    int bk = t >> 3, bn = (t & 7) * 8;
    const float* Bp = Vb + (size_t)bk * QKVC + bn;
    float c[4][4][4] = {};
    for (int kk = 0; kk < SEQ; kk += 16) {
        uint4 ap0 = *(const uint4*)(Arow + kk);
        uint4 ap1 = *(const uint4*)(Arow + kk + 8);
        float4 b0 = *(const float4*)Bp;
        float4 b1 = *(const float4*)(Bp + 4);
        Bp += (size_t)16 * QKVC;
        __syncthreads();
        {
            const uint32_t aw[8] = {ap0.x, ap0.y, ap0.z, ap0.w, ap1.x, ap1.y, ap1.z, ap1.w};
            #pragma unroll
            for (int p = 0; p < 8; p++) {
                __half2 hv = *(const __half2*)&aw[p];
                float2 fv = __half22float2(hv);
                As[2*p][t]   = f2tf32(fv.x);
                As[2*p+1][t] = f2tf32(fv.y);
            }
        }
        *(uint4*)&Bs[bk][bn]   = make_uint4(f2tf32(b0.x), f2tf32(b0.y), f2tf32(b0.z), f2tf32(b0.w));
        *(uint4*)&Bs[bk][bn+4] = make_uint4(f2tf32(b1.x), f2tf32(b1.y), f2tf32(b1.z), f2tf32(b1.w));
        __syncthreads();
        #pragma unroll
        for (int ks = 0; ks < 2; ks++) {
            int kr = ks * 8 + (lane & 3);
            int mr = wm + (lane >> 2);
            int nr = wn + (lane >> 2);
            uint32_t af[4][4], bf[4][2];
            #pragma unroll
            for (int mt = 0; mt < 4; mt++) {
                af[mt][0] = As[kr][mr + mt*16];
                af[mt][1] = As[kr][mr + mt*16 + 8];
                af[mt][2] = As[kr+4][mr + mt*16];
                af[mt][3] = As[kr+4][mr + mt*16 + 8];
            }
            #pragma unroll
            for (int nt = 0; nt < 4; nt++) {
                bf[nt][0] = Bs[kr][nr + nt*8];
                bf[nt][1] = Bs[kr+4][nr + nt*8];
            }
            #pragma unroll
            for (int mt = 0; mt < 4; mt++)
                #pragma unroll
                for (int nt = 0; nt < 4; nt++)
                    MMA_TF32(c[mt][nt], af[mt], bf[nt]);
        }
    }
    int col0 = wn + 2 * (lane & 3);
    int row0 = m0 + wm + (lane >> 2);
    #pragma unroll
    for (int mt = 0; mt < 4; mt++)
        #pragma unroll
        for (int nt = 0; nt < 4; nt++) {
            float* Cp = g_ao + ((size_t)z * SEQ + row0 + mt*16) * DH + col0 + nt*8;
            *(float2*)Cp = make_float2(c[mt][nt][0], c[mt][nt][1]);
            *(float2*)(Cp + (size_t)8 * DH) = make_float2(c[mt][nt][2], c[mt][nt][3]);
        }
}

// ============================================================ out = O @ Wout + bout (R2 engine)
__global__ __launch_bounds__(256)
void out_mma_kernel(const float* __restrict__ Wout, const float* __restrict__ bout,
                    float* __restrict__ out) {
    __shared__ uint32_t As[16][136];
    __shared__ uint32_t Bs[16][136];
    int t = threadIdx.x, lane = t & 31, w = t >> 5;
    int wm = (w & 1) * 64, wn = (w >> 1) * 32;
    int m0 = blockIdx.y * 128, n0 = blockIdx.x * 128;
    int sa_m = t >> 1, sa_k = (t & 1) * 8;
    int sb_k = t >> 4, sb_n = (t & 15) * 8;
    int row = m0 + sa_m;
    int bb = row >> 11, ii = row & (SEQ - 1);
    const float* Bptr = Wout + (size_t)sb_k * DIMC + n0 + sb_n;
    float c[4][4][4] = {};
    for (int kk = 0; kk < DIMC; kk += 16) {
        int k = kk + sa_k;
        int gh = k >> 6, d = k & 63;
        const float* Ap = g_ao + ((size_t)(bb * NH + gh) * SEQ + ii) * DH + d;
        float4 a0 = *(const float4*)Ap;
        float4 a1 = *(const float4*)(Ap + 4);
        float4 b0 = *(const float4*)Bptr;
        float4 b1 = *(const float4*)(Bptr + 4);
        Bptr += (size_t)16 * DIMC;
        As[sa_k+0][sa_m] = f2tf32(a0.x); As[sa_k+1][sa_m] = f2tf32(a0.y);
        As[sa_k+2][sa_m] = f2tf32(a0.z); As[sa_k+3][sa_m] = f2tf32(a0.w);
        As[sa_k+4][sa_m] = f2tf32(a1.x); As[sa_k+5][sa_m] = f2tf32(a1.y);
        As[sa_k+6][sa_m] = f2tf32(a1.z); As[sa_k+7][sa_m] = f2tf32(a1.w);
        *(uint4*)&Bs[sb_k][sb_n]   = make_uint4(f2tf32(b0.x), f2tf32(b0.y), f2tf32(b0.z), f2tf32(b0.w));
        *(uint4*)&Bs[sb_k][sb_n+4] = make_uint4(f2tf32(b1.x), f2tf32(b1.y), f2tf32(b1.z), f2tf32(b1.w));
        __syncthreads();
        #pragma unroll
        for (int ks = 0; ks < 2; ks++) {
            int kr = ks * 8 + (lane & 3);
            int mr = wm + (lane >> 2);
            int nr = wn + (lane >> 2);
            uint32_t af[4][4], bf[4][2];
            #pragma unroll
            for (int mt = 0; mt < 4; mt++) {
                af[mt][0] = As[kr][mr + mt*16];
                af[mt][1] = As[kr][mr + mt*16 + 8];
                af[mt][2] = As[kr+4][mr + mt*16];
                af[mt][3] = As[kr+4][mr + mt*16 + 8];
            }
            #pragma unroll
            for (int nt = 0; nt < 4; nt++) {
                bf[nt][0] = Bs[kr][nr + nt*8];
                bf[nt][1] = Bs[kr+4][nr + nt*8];
            }
            #pragma unroll
            for (int mt = 0; mt < 4; mt++)
                #pragma unroll
                for (int nt = 0; nt < 4; nt++)
                    MMA_TF32(c[mt][nt], af[mt], bf[nt]);
        }
        __syncthreads();
    }
    int col0 = n0 + wn + 2 * (lane & 3);
    int row0 = m0 + wm + (lane >> 2);
    #pragma unroll
    for (int nt = 0; nt < 4; nt++) {
        float b0v = bout[col0 + nt*8];
        float b1v = bout[col0 + nt*8 + 1];
        #pragma unroll
        for (int mt = 0; mt < 4; mt++) {
            float* Cp = out + (size_t)(row0 + mt*16) * DIMC + col0 + nt*8;
            *(float2*)Cp = make_float2(c[mt][nt][0] + b0v, c[mt][nt][1] + b1v);
            *(float2*)(Cp + (size_t)8 * DIMC) = make_float2(c[mt][nt][2] + b0v, c[mt][nt][3] + b1v);
        }
    }
}

// ============================================================ launch: 2-stream batch pipeline
extern "C" void kernel_launch(void* const* d_in, const int* in_sizes, int n_in,
                              void* d_out, int out_size) {
    const float* x       = (const float*)d_in[0];
    const float* ln_g    = (const float*)d_in[1];
    const float* ln_b    = (const float*)d_in[2];
    const float* Wq      = (const float*)d_in[3];
    const float* Wkv     = (const float*)d_in[4];
    const float* mixpre  = (const float*)d_in[5];
    const float* mixpost = (const float*)d_in[6];
    const float* Wout    = (const float*)d_in[7];
    const float* bout    = (const float*)d_in[8];
    float* out = (float*)d_out;

    const int MIXSMEM = NH * PITCH * 4;   // 131584
    static bool init0 = false;
    static cudaStream_t s1;
    static cudaEvent_t evRoot, evQ0, evQ1, evM0, evM1;
    if (!init0) {
        cudaStreamCreateWithFlags(&s1, cudaStreamNonBlocking);
        cudaEventCreateWithFlags(&evRoot, cudaEventDisableTiming);
        cudaEventCreateWithFlags(&evQ0, cudaEventDisableTiming);
        cudaEventCreateWithFlags(&evQ1, cudaEventDisableTiming);
        cudaEventCreateWithFlags(&evM0, cudaEventDisableTiming);
        cudaEventCreateWithFlags(&evM1, cudaEventDisableTiming);
        cudaFuncSetAttribute(mixsoftmax_kernel,
                             cudaFuncAttributeMaxDynamicSharedMemorySize, MIXSMEM);
        init0 = true;
    }

    cudaEventRecord(evRoot, 0);
    cudaStreamWaitEvent(s1, evRoot, 0);

    ln_kernel<<<NROWS, 256>>>(x, ln_g, ln_b);
    proj_mma_kernel<<<dim3(24, 32), 256>>>(Wq, Wkv);

    qk_mma_kernel<<<dim3(16, 16, 16), 256>>>(0);
    cudaEventRecord(evQ0, 0);
    qk_mma_kernel<<<dim3(16, 16, 16), 256>>>(1);
    cudaEventRecord(evQ1, 0);

    cudaStreamWaitEvent(s1, evQ0, 0);
    mixsoftmax_kernel<<<SEQ, 512, MIXSMEM, s1>>>(mixpre, mixpost, 0);
    cudaEventRecord(evM0, s1);
    cudaStreamWaitEvent(s1, evQ1, 0);
    mixsoftmax_kernel<<<SEQ, 512, MIXSMEM, s1>>>(mixpre, mixpost, 1);
    cudaEventRecord(evM1, s1);

    cudaStreamWaitEvent(0, evM0, 0);
    av_mma_kernel<<<dim3(16, 16), 128>>>(0);
    cudaStreamWaitEvent(0, evM1, 0);
    av_mma_kernel<<<dim3(16, 16), 128>>>(1);

    out_mma_kernel<<<dim3(8, 32), 256>>>(Wout, bout, out);
}

// round 16
// speedup vs baseline: 1.1072x; 1.1072x over previous
#include <cuda_runtime.h>
#include <cuda_fp16.h>
#include <cstdint>

#define BQ   2
#define SEQ  2048
#define DIMC 1024
#define NH   16
#define DH   64
#define QKVC 3072
#define NROWS (BQ*SEQ)
#define PITCH 2056

// ---- device scratch ----
__device__ float  g_xn[(size_t)NROWS * DIMC];            // 16 MB
__device__ float  g_qkv[(size_t)NROWS * QKVC];           // 48 MB  [q | k | v]
__device__ float  g_dots[(size_t)BQ * NH * SEQ * SEQ];   // 512 MB (raw dots)
__device__ __half g_prh[(size_t)BQ * NH * SEQ * SEQ];    // 256 MB (post-mix probs fp16)
__device__ float  g_ao[(size_t)BQ * NH * SEQ * DH];      // 16 MB  [b,g,i,d]

__device__ __forceinline__ uint32_t f2tf32(float f) {
    uint32_t u; asm("cvt.rna.tf32.f32 %0, %1;" : "=r"(u) : "f"(f)); return u;
}
__device__ __forceinline__ void spl(float v, uint32_t& h, uint32_t& l) {
    uint32_t hb = f2tf32(v);
    h = hb;
    l = f2tf32(v - __uint_as_float(hb));
}

#define MMA_TF32(c, a, b) \
    asm volatile("mma.sync.aligned.m16n8k8.row.col.f32.tf32.tf32.f32 " \
        "{%0,%1,%2,%3}, {%4,%5,%6,%7}, {%8,%9}, {%0,%1,%2,%3};" \
        : "+f"((c)[0]), "+f"((c)[1]), "+f"((c)[2]), "+f"((c)[3]) \
        : "r"((a)[0]), "r"((a)[1]), "r"((a)[2]), "r"((a)[3]), \
          "r"((b)[0]), "r"((b)[1]))

// ============================================================ LayerNorm
__global__ void ln_kernel(const float* __restrict__ x,
                          const float* __restrict__ gamma,
                          const float* __restrict__ beta) {
    int row = blockIdx.x;
    int t = threadIdx.x;
    const float4* xr = (const float4*)(x + (size_t)row * DIMC);
    float4 v = xr[t];
    float s = v.x + v.y + v.z + v.w;
    float q = v.x*v.x + v.y*v.y + v.z*v.z + v.w*v.w;
    __shared__ float s_sum[8], s_sq[8];
    #pragma unroll
    for (int o = 16; o > 0; o >>= 1) {
        s += __shfl_xor_sync(0xffffffffu, s, o);
        q += __shfl_xor_sync(0xffffffffu, q, o);
    }
    if ((t & 31) == 0) { s_sum[t >> 5] = s; s_sq[t >> 5] = q; }
    __syncthreads();
    if (t < 32) {
        float a = (t < 8) ? s_sum[t] : 0.f;
        float c = (t < 8) ? s_sq[t] : 0.f;
        #pragma unroll
        for (int o = 4; o > 0; o >>= 1) {
            a += __shfl_xor_sync(0xffffffffu, a, o);
            c += __shfl_xor_sync(0xffffffffu, c, o);
        }
        if (t == 0) { s_sum[0] = a; s_sq[0] = c; }
    }
    __syncthreads();
    float mean = s_sum[0] * (1.f / DIMC);
    float var  = s_sq[0] * (1.f / DIMC) - mean * mean;
    float rs = rsqrtf(var + 1e-5f);
    float4 gg = ((const float4*)gamma)[t];
    float4 bb = ((const float4*)beta)[t];
    float4 o;
    o.x = (v.x - mean) * rs * gg.x + bb.x;
    o.y = (v.y - mean) * rs * gg.y + bb.y;
    o.z = (v.z - mean) * rs * gg.z + bb.z;
    o.w = (v.w - mean) * rs * gg.w + bb.w;
    ((float4*)(g_xn + (size_t)row * DIMC))[t] = o;
}

// ============================================================ QKV projection (TF32 MMA)
__global__ __launch_bounds__(256)
void proj_mma_kernel(const float* __restrict__ Wq, const float* __restrict__ Wkv) {
    __shared__ uint32_t As[16][136];
    __shared__ uint32_t Bs[16][136];
    int t = threadIdx.x, lane = t & 31, w = t >> 5;
    int wm = (w & 1) * 64, wn = (w >> 1) * 32;
    int cb = blockIdx.x * 128;
    const float* Bp; int ldb;
    if (cb < 1024) { Bp = Wq; ldb = 1024; } else { Bp = Wkv; ldb = 2048; cb -= 1024; }
    int m0 = blockIdx.y * 128;
    int sa_m = t >> 1, sa_k = (t & 1) * 8;
    int sb_k = t >> 4, sb_n = (t & 15) * 8;
    const float* Aptr = g_xn + (size_t)(m0 + sa_m) * DIMC + sa_k;
    const float* Bptr = Bp + (size_t)sb_k * ldb + cb + sb_n;
    float c[4][4][4] = {};
    for (int kk = 0; kk < DIMC; kk += 16) {
        float4 a0 = *(const float4*)Aptr;
        float4 a1 = *(const float4*)(Aptr + 4);
        Aptr += 16;
        float4 b0 = *(const float4*)Bptr;
        float4 b1 = *(const float4*)(Bptr + 4);
        Bptr += (size_t)16 * ldb;
        As[sa_k+0][sa_m] = f2tf32(a0.x); As[sa_k+1][sa_m] = f2tf32(a0.y);
        As[sa_k+2][sa_m] = f2tf32(a0.z); As[sa_k+3][sa_m] = f2tf32(a0.w);
        As[sa_k+4][sa_m] = f2tf32(a1.x); As[sa_k+5][sa_m] = f2tf32(a1.y);
        As[sa_k+6][sa_m] = f2tf32(a1.z); As[sa_k+7][sa_m] = f2tf32(a1.w);
        *(uint4*)&Bs[sb_k][sb_n]   = make_uint4(f2tf32(b0.x), f2tf32(b0.y), f2tf32(b0.z), f2tf32(b0.w));
        *(uint4*)&Bs[sb_k][sb_n+4] = make_uint4(f2tf32(b1.x), f2tf32(b1.y), f2tf32(b1.z), f2tf32(b1.w));
        __syncthreads();
        #pragma unroll
        for (int ks = 0; ks < 2; ks++) {
            int kr = ks * 8 + (lane & 3);
            int mr = wm + (lane >> 2);
            int nr = wn + (lane >> 2);
            uint32_t af[4][4], bf[4][2];
            #pragma unroll
            for (int mt = 0; mt < 4; mt++) {
                af[mt][0] = As[kr][mr + mt*16];
                af[mt][1] = As[kr][mr + mt*16 + 8];
                af[mt][2] = As[kr+4][mr + mt*16];
                af[mt][3] = As[kr+4][mr + mt*16 + 8];
            }
            #pragma unroll
            for (int nt = 0; nt < 4; nt++) {
                bf[nt][0] = Bs[kr][nr + nt*8];
                bf[nt][1] = Bs[kr+4][nr + nt*8];
            }
            #pragma unroll
            for (int mt = 0; mt < 4; mt++)
                #pragma unroll
                for (int nt = 0; nt < 4; nt++)
                    MMA_TF32(c[mt][nt], af[mt], bf[nt]);
        }
        __syncthreads();
    }
    int col0 = blockIdx.x * 128 + wn + 2 * (lane & 3);
    int row0 = m0 + wm + (lane >> 2);
    #pragma unroll
    for (int mt = 0; mt < 4; mt++)
        #pragma unroll
        for (int nt = 0; nt < 4; nt++) {
            float* Cp = g_qkv + (size_t)(row0 + mt*16) * QKVC + col0 + nt*8;
            *(float2*)Cp = make_float2(c[mt][nt][0], c[mt][nt][1]);
            *(float2*)(Cp + (size_t)8 * QKVC) = make_float2(c[mt][nt][2], c[mt][nt][3]);
        }
}

// ============================================================ S = scale * Q K^T
__global__ __launch_bounds__(256)
void qk_mma_kernel() {
    __shared__ uint32_t As[16][136];
    __shared__ uint32_t Bs[16][136];
    int t = threadIdx.x, lane = t & 31, w = t >> 5;
    int wm = (w & 1) * 64, wn = (w >> 1) * 32;
    int z = blockIdx.z, b = z >> 4, h = z & 15;
    const float* Qb = g_qkv + (size_t)b * SEQ * QKVC + h * DH;
    const float* Kb = Qb + 1024;
    int m0 = blockIdx.y * 128, n0 = blockIdx.x * 128;
    int sm = t >> 1, sk = (t & 1) * 8;
    const float* Ap  = Qb + (size_t)(m0 + sm) * QKVC + sk;
    const float* Bp  = Kb + (size_t)(n0 + sm) * QKVC + sk;
    float c[4][4][4] = {};
    for (int kk = 0; kk < DH; kk += 16) {
        float4 a0 = *(const float4*)Ap;
        float4 a1 = *(const float4*)(Ap + 4);
        Ap += 16;
        float4 k0 = *(const float4*)Bp;
        float4 k1 = *(const float4*)(Bp + 4);
        Bp += 16;
        As[sk+0][sm] = f2tf32(a0.x); As[sk+1][sm] = f2tf32(a0.y);
        As[sk+2][sm] = f2tf32(a0.z); As[sk+3][sm] = f2tf32(a0.w);
        As[sk+4][sm] = f2tf32(a1.x); As[sk+5][sm] = f2tf32(a1.y);
        As[sk+6][sm] = f2tf32(a1.z); As[sk+7][sm] = f2tf32(a1.w);
        Bs[sk+0][sm] = f2tf32(k0.x); Bs[sk+1][sm] = f2tf32(k0.y);
        Bs[sk+2][sm] = f2tf32(k0.z); Bs[sk+3][sm] = f2tf32(k0.w);
        Bs[sk+4][sm] = f2tf32(k1.x); Bs[sk+5][sm] = f2tf32(k1.y);
        Bs[sk+6][sm] = f2tf32(k1.z); Bs[sk+7][sm] = f2tf32(k1.w);
        __syncthreads();
        #pragma unroll
        for (int ks = 0; ks < 2; ks++) {
            int kr = ks * 8 + (lane & 3);
            int mr = wm + (lane >> 2);
            int nr = wn + (lane >> 2);
            uint32_t af[4][4], bf[4][2];
            #pragma unroll
            for (int mt = 0; mt < 4; mt++) {
                af[mt][0] = As[kr][mr + mt*16];
                af[mt][1] = As[kr][mr + mt*16 + 8];
                af[mt][2] = As[kr+4][mr + mt*16];
                af[mt][3] = As[kr+4][mr + mt*16 + 8];
            }
            #pragma unroll
            for (int nt = 0; nt < 4; nt++) {
                bf[nt][0] = Bs[kr][nr + nt*8];
                bf[nt][1] = Bs[kr+4][nr + nt*8];
            }
            #pragma unroll
            for (int mt = 0; mt < 4; mt++)
                #pragma unroll
                for (int nt = 0; nt < 4; nt++)
                    MMA_TF32(c[mt][nt], af[mt], bf[nt]);
        }
        __syncthreads();
    }
    const float scale = 0.125f;
    int col0 = n0 + wn + 2 * (lane & 3);
    int row0 = m0 + wm + (lane >> 2);
    #pragma unroll
    for (int mt = 0; mt < 4; mt++)
        #pragma unroll
        for (int nt = 0; nt < 4; nt++) {
            float* Cp = g_dots + ((size_t)z * SEQ + row0 + mt*16) * SEQ + col0 + nt*8;
            *(float2*)Cp = make_float2(c[mt][nt][0]*scale, c[mt][nt][1]*scale);
            *(float2*)(Cp + (size_t)8 * SEQ) = make_float2(c[mt][nt][2]*scale, c[mt][nt][3]*scale);
        }
}

// ============================================================ mix (MMA) -> softmax -> mix (MMA)
// 512 threads (16 warps); reads g_dots f32, writes g_prh fp16
__global__ __launch_bounds__(512)
void mixsoftmax_kernel(const float* __restrict__ mix_pre, const float* __restrict__ mix_post) {
    extern __shared__ float srow[];          // [NH][PITCH]
    __shared__ float mps[256], mqs[256];
    __shared__ float red[NH][16];
    __shared__ float mg[NH], ssum[NH], linv[NH];
    int t = threadIdx.x, lane = t & 31, w = t >> 5;
    int g0 = lane >> 2, h0 = lane & 3;
    int b = blockIdx.x >> 11;
    int i = blockIdx.x & (SEQ - 1);
    if (t < 256) { mps[t] = mix_pre[t]; mqs[t] = mix_post[t]; }
    size_t base = ((size_t)(b * NH) * SEQ + i) * SEQ;
    for (int h = 0; h < NH; h++) {
        const float4* src = (const float4*)(g_dots + base + (size_t)h * SEQ * SEQ);
        float4* dst = (float4*)(srow + h * PITCH);
        for (int j = t; j < SEQ/4; j += 512) dst[j] = src[j];
    }
    __syncthreads();

    uint32_t pah[2][4], pal[2][4];
    #pragma unroll
    for (int ks = 0; ks < 2; ks++) {
        int hh = h0 + ks * 8;
        spl(mps[hh*16 + g0],        pah[ks][0], pal[ks][0]);
        spl(mps[hh*16 + g0 + 8],    pah[ks][1], pal[ks][1]);
        spl(mps[(hh+4)*16 + g0],    pah[ks][2], pal[ks][2]);
        spl(mps[(hh+4)*16 + g0 + 8],pah[ks][3], pal[ks][3]);
    }
    float pm0 = -3.4e38f, pm1 = -3.4e38f;
    for (int tile = 0; tile < 16; tile++) {
        int j0 = (w * 16 + tile) * 8;
        int col = j0 + g0;
        uint32_t bh[2][2], bl[2][2];
        spl(srow[h0*PITCH + col],        bh[0][0], bl[0][0]);
        spl(srow[(h0+4)*PITCH + col],    bh[0][1], bl[0][1]);
        spl(srow[(h0+8)*PITCH + col],    bh[1][0], bl[1][0]);
        spl(srow[(h0+12)*PITCH + col],   bh[1][1], bl[1][1]);
        float c[4] = {0.f, 0.f, 0.f, 0.f};
        #pragma unroll
        for (int ks = 0; ks < 2; ks++) {
            MMA_TF32(c, pah[ks], bh[ks]);
            MMA_TF32(c, pah[ks], bl[ks]);
            MMA_TF32(c, pal[ks], bh[ks]);
        }
        __syncwarp();
        *(float2*)&srow[g0*PITCH + j0 + 2*h0]     = make_float2(c[0], c[1]);
        *(float2*)&srow[(g0+8)*PITCH + j0 + 2*h0] = make_float2(c[2], c[3]);
        pm0 = fmaxf(pm0, fmaxf(c[0], c[1]));
        pm1 = fmaxf(pm1, fmaxf(c[2], c[3]));
    }
    pm0 = fmaxf(pm0, __shfl_xor_sync(0xffffffffu, pm0, 1));
    pm0 = fmaxf(pm0, __shfl_xor_sync(0xffffffffu, pm0, 2));
    pm1 = fmaxf(pm1, __shfl_xor_sync(0xffffffffu, pm1, 1));
    pm1 = fmaxf(pm1, __shfl_xor_sync(0xffffffffu, pm1, 2));
    if (h0 == 0) { red[g0][w] = pm0; red[g0 + 8][w] = pm1; }
    __syncthreads();
    if (t < NH) {
        float v = red[t][0];
        #pragma unroll
        for (int w2 = 1; w2 < 16; w2++) v = fmaxf(v, red[t][w2]);
        mg[t] = v;
    }
    __syncthreads();
    {
        int r = w;
        float m = mg[r];
        float s = 0.f;
        float* rp = srow + r * PITCH;
        #pragma unroll 4
        for (int i2 = 0; i2 < 16; i2++) {
            int j4 = (lane + i2 * 32) * 4;
            float4 v = *(float4*)&rp[j4];
            v.x = __expf(v.x - m); v.y = __expf(v.y - m);
            v.z = __expf(v.z - m); v.w = __expf(v.w - m);
            s += (v.x + v.y) + (v.z + v.w);
            *(float4*)&rp[j4] = v;
        }
        #pragma unroll
        for (int o = 16; o > 0; o >>= 1) s += __shfl_xor_sync(0xffffffffu, s, o);
        if (lane == 0) ssum[r] = s;
    }
    __syncthreads();
    if (t < NH) linv[t] = 1.f / ssum[t];
    __syncthreads();
    uint32_t qah[2][4], qal[2][4];
    #pragma unroll
    for (int ks = 0; ks < 2; ks++) {
        int hh = h0 + ks * 8;
        spl(mqs[hh*16 + g0]         * linv[hh],   qah[ks][0], qal[ks][0]);
        spl(mqs[hh*16 + g0 + 8]     * linv[hh],   qah[ks][1], qal[ks][1]);
        spl(mqs[(hh+4)*16 + g0]     * linv[hh+4], qah[ks][2], qal[ks][2]);
        spl(mqs[(hh+4)*16 + g0 + 8] * linv[hh+4], qah[ks][3], qal[ks][3]);
    }
    for (int tile = 0; tile < 16; tile++) {
        int j0 = (w * 16 + tile) * 8;
        int col = j0 + g0;
        uint32_t bh[2][2], bl[2][2];
        spl(srow[h0*PITCH + col],        bh[0][0], bl[0][0]);
        spl(srow[(h0+4)*PITCH + col],    bh[0][1], bl[0][1]);
        spl(srow[(h0+8)*PITCH + col],    bh[1][0], bl[1][0]);
        spl(srow[(h0+12)*PITCH + col],   bh[1][1], bl[1][1]);
        float c[4] = {0.f, 0.f, 0.f, 0.f};
        #pragma unroll
        for (int ks = 0; ks < 2; ks++) {
            MMA_TF32(c, qah[ks], bh[ks]);
            MMA_TF32(c, qah[ks], bl[ks]);
            MMA_TF32(c, qal[ks], bh[ks]);
        }
        __half* Cp = g_prh + base + (size_t)g0 * SEQ * SEQ + j0 + 2*h0;
        *(__half2*)Cp = __floats2half2_rn(c[0], c[1]);
        *(__half2*)(Cp + (size_t)8 * SEQ * SEQ) = __floats2half2_rn(c[2], c[3]);
    }
}

// ============================================================ O = P @ V  (CTA 128x64, 4 warps 64x32; A fp16)
__global__ __launch_bounds__(128)
void av_mma_kernel() {
    __shared__ uint32_t As[16][136];
    __shared__ uint32_t Bs[16][72];
    int t = threadIdx.x, lane = t & 31, w = t >> 5;
    int wm = (w & 1) * 64, wn = (w >> 1) * 32;
    int z = blockIdx.y, b = z >> 4, g = z & 15;
    const __half* Am = g_prh + (size_t)z * SEQ * SEQ;
    const float* Vb = g_qkv + (size_t)b * SEQ * QKVC + 2048 + g * DH;
    int m0 = blockIdx.x * 128;
    const __half* Arow = Am + (size_t)(m0 + t) * SEQ;
    int bk = t >> 3, bn = (t & 7) * 8;
    const float* Bp = Vb + (size_t)bk * QKVC + bn;
    float c[4][4][4] = {};
    for (int kk = 0; kk < SEQ; kk += 16) {
        uint4 ap0 = *(const uint4*)(Arow + kk);
        uint4 ap1 = *(const uint4*)(Arow + kk + 8);
        float4 b0 = *(const float4*)Bp;
        float4 b1 = *(const float4*)(Bp + 4);
        Bp += (size_t)16 * QKVC;
        __syncthreads();
        {
            const uint32_t aw[8] = {ap0.x, ap0.y, ap0.z, ap0.w, ap1.x, ap1.y, ap1.z, ap1.w};
            #pragma unroll
            for (int p = 0; p < 8; p++) {
                __half2 hv = *(const __half2*)&aw[p];
                float2 fv = __half22float2(hv);
                As[2*p][t]   = f2tf32(fv.x);
                As[2*p+1][t] = f2tf32(fv.y);
            }
        }
        *(uint4*)&Bs[bk][bn]   = make_uint4(f2tf32(b0.x), f2tf32(b0.y), f2tf32(b0.z), f2tf32(b0.w));
        *(uint4*)&Bs[bk][bn+4] = make_uint4(f2tf32(b1.x), f2tf32(b1.y), f2tf32(b1.z), f2tf32(b1.w));
        __syncthreads();
        #pragma unroll
        for (int ks = 0; ks < 2; ks++) {
            int kr = ks * 8 + (lane & 3);
            int mr = wm + (lane >> 2);
            int nr = wn + (lane >> 2);
            uint32_t af[4][4], bf[4][2];
            #pragma unroll
            for (int mt = 0; mt < 4; mt++) {
                af[mt][0] = As[kr][mr + mt*16];
                af[mt][1] = As[kr][mr + mt*16 + 8];
                af[mt][2] = As[kr+4][mr + mt*16];
                af[mt][3] = As[kr+4][mr + mt*16 + 8];
            }
            #pragma unroll
            for (int nt = 0; nt < 4; nt++) {
                bf[nt][0] = Bs[kr][nr + nt*8];
                bf[nt][1] = Bs[kr+4][nr + nt*8];
            }
            #pragma unroll
            for (int mt = 0; mt < 4; mt++)
                #pragma unroll
                for (int nt = 0; nt < 4; nt++)
                    MMA_TF32(c[mt][nt], af[mt], bf[nt]);
        }
    }
    int col0 = wn + 2 * (lane & 3);
    int row0 = m0 + wm + (lane >> 2);
    #pragma unroll
    for (int mt = 0; mt < 4; mt++)
        #pragma unroll
        for (int nt = 0; nt < 4; nt++) {
            float* Cp = g_ao + ((size_t)z * SEQ + row0 + mt*16) * DH + col0 + nt*8;
            *(float2*)Cp = make_float2(c[mt][nt][0], c[mt][nt][1]);
            *(float2*)(Cp + (size_t)8 * DH) = make_float2(c[mt][nt][2], c[mt][nt][3]);
        }
}

// ============================================================ out = O @ Wout + bout
__global__ __launch_bounds__(256)
void out_mma_kernel(const float* __restrict__ Wout, const float* __restrict__ bout,
                    float* __restrict__ out) {
    __shared__ uint32_t As[16][136];
    __shared__ uint32_t Bs[16][136];
    int t = threadIdx.x, lane = t & 31, w = t >> 5;
    int wm = (w & 1) * 64, wn = (w >> 1) * 32;
    int m0 = blockIdx.y * 128, n0 = blockIdx.x * 128;
    int sa_m = t >> 1, sa_k = (t & 1) * 8;
    int sb_k = t >> 4, sb_n = (t & 15) * 8;
    int row = m0 + sa_m;
    int bb = row >> 11, ii = row & (SEQ - 1);
    const float* Bptr = Wout + (size_t)sb_k * DIMC + n0 + sb_n;
    float c[4][4][4] = {};
    for (int kk = 0; kk < DIMC; kk += 16) {
        int k = kk + sa_k;
        int gh = k >> 6, d = k & 63;
        const float* Ap = g_ao + ((size_t)(bb * NH + gh) * SEQ + ii) * DH + d;
        float4 a0 = *(const float4*)Ap;
        float4 a1 = *(const float4*)(Ap + 4);
        float4 b0 = *(const float4*)Bptr;
        float4 b1 = *(const float4*)(Bptr + 4);
        Bptr += (size_t)16 * DIMC;
        As[sa_k+0][sa_m] = f2tf32(a0.x); As[sa_k+1][sa_m] = f2tf32(a0.y);
        As[sa_k+2][sa_m] = f2tf32(a0.z); As[sa_k+3][sa_m] = f2tf32(a0.w);
        As[sa_k+4][sa_m] = f2tf32(a1.x); As[sa_k+5][sa_m] = f2tf32(a1.y);
        As[sa_k+6][sa_m] = f2tf32(a1.z); As[sa_k+7][sa_m] = f2tf32(a1.w);
        *(uint4*)&Bs[sb_k][sb_n]   = make_uint4(f2tf32(b0.x), f2tf32(b0.y), f2tf32(b0.z), f2tf32(b0.w));
        *(uint4*)&Bs[sb_k][sb_n+4] = make_uint4(f2tf32(b1.x), f2tf32(b1.y), f2tf32(b1.z), f2tf32(b1.w));
        __syncthreads();
        #pragma unroll
        for (int ks = 0; ks < 2; ks++) {
            int kr = ks * 8 + (lane & 3);
            int mr = wm + (lane >> 2);
            int nr = wn + (lane >> 2);
            uint32_t af[4][4], bf[4][2];
            #pragma unroll
            for (int mt = 0; mt < 4; mt++) {
                af[mt][0] = As[kr][mr + mt*16];
                af[mt][1] = As[kr][mr + mt*16 + 8];
                af[mt][2] = As[kr+4][mr + mt*16];
                af[mt][3] = As[kr+4][mr + mt*16 + 8];
            }
            #pragma unroll
            for (int nt = 0; nt < 4; nt++) {
                bf[nt][0] = Bs[kr][nr + nt*8];
                bf[nt][1] = Bs[kr+4][nr + nt*8];
            }
            #pragma unroll
            for (int mt = 0; mt < 4; mt++)
                #pragma unroll
                for (int nt = 0; nt < 4; nt++)
                    MMA_TF32(c[mt][nt], af[mt], bf[nt]);
        }
        __syncthreads();
    }
    int col0 = n0 + wn + 2 * (lane & 3);
    int row0 = m0 + wm + (lane >> 2);
    #pragma unroll
    for (int nt = 0; nt < 4; nt++) {
        float b0v = bout[col0 + nt*8];
        float b1v = bout[col0 + nt*8 + 1];
        #pragma unroll
        for (int mt = 0; mt < 4; mt++) {
            float* Cp = out + (size_t)(row0 + mt*16) * DIMC + col0 + nt*8;
            *(float2*)Cp = make_float2(c[mt][nt][0] + b0v, c[mt][nt][1] + b1v);
            *(float2*)(Cp + (size_t)8 * DIMC) = make_float2(c[mt][nt][2] + b0v, c[mt][nt][3] + b1v);
        }
    }
}

// ============================================================ launch (serial, single stream)
extern "C" void kernel_launch(void* const* d_in, const int* in_sizes, int n_in,
                              void* d_out, int out_size) {
    const float* x       = (const float*)d_in[0];
    const float* ln_g    = (const float*)d_in[1];
    const float* ln_b    = (const float*)d_in[2];
    const float* Wq      = (const float*)d_in[3];
    const float* Wkv     = (const float*)d_in[4];
    const float* mixpre  = (const float*)d_in[5];
    const float* mixpost = (const float*)d_in[6];
    const float* Wout    = (const float*)d_in[7];
    const float* bout    = (const float*)d_in[8];
    float* out = (float*)d_out;

    const int MIXSMEM = NH * PITCH * 4;   // 131584
    cudaFuncSetAttribute(mixsoftmax_kernel,
                         cudaFuncAttributeMaxDynamicSharedMemorySize, MIXSMEM);

    ln_kernel<<<NROWS, 256>>>(x, ln_g, ln_b);
    proj_mma_kernel<<<dim3(24, 32), 256>>>(Wq, Wkv);
    qk_mma_kernel<<<dim3(16, 16, 32), 256>>>();
    mixsoftmax_kernel<<<BQ * SEQ, 512, MIXSMEM>>>(mixpre, mixpost);
    av_mma_kernel<<<dim3(16, 32), 128>>>();
    out_mma_kernel<<<dim3(8, 32), 256>>>(Wout, bout, out);
}